// round 3
// baseline (speedup 1.0000x reference)
#include <cuda_runtime.h>
#include <math.h>

#define N_NODES   50000
#define N_EDGES   1600000
#define N_FEAT    128
#define EMB       128
#define N_CLASSES 10
#define N_GRAPHS  512

// ---------------- device scratch (static, no runtime allocation) ----------------
__device__ int   g_deg[N_NODES];
__device__ int   g_rowptr[N_NODES + 1];
__device__ int   g_cursor[N_NODES];
__device__ int   g_col[N_EDGES];
__device__ float g_dis[N_NODES];                 // deg^{-1/2} (incl. self loop)
__device__ float g_bufA[(size_t)N_NODES * EMB];  // GEMM output (pre-aggregation)
__device__ float g_bufB[(size_t)N_NODES * EMB];  // activation (post-aggregation)
__device__ float g_pooled[N_GRAPHS * EMB];

// ---------------- CSR build ----------------
__global__ void k_zero_deg() {
    int i = blockIdx.x * blockDim.x + threadIdx.x;
    if (i < N_NODES) g_deg[i] = 0;
}

__global__ void k_hist(const int* __restrict__ ei) {
    int i = blockIdx.x * blockDim.x + threadIdx.x;
    if (i < N_EDGES) {
        int d = ei[N_EDGES + i];   // dst row of edge_index
        atomicAdd(&g_deg[d], 1);
    }
}

// single block, 1024 threads: exclusive scan of g_deg -> g_rowptr/g_cursor, dis
__global__ void k_scan() {
    __shared__ int part[1024];
    const int t = threadIdx.x;
    const int CH = (N_NODES + 1023) / 1024;   // 49
    int beg = t * CH;
    int end = beg + CH; if (end > N_NODES) end = N_NODES;
    if (beg > N_NODES) beg = N_NODES;

    int s = 0;
    for (int i = beg; i < end; ++i) s += g_deg[i];
    part[t] = s;
    __syncthreads();
    // inclusive Hillis-Steele scan over 1024 partials
    for (int off = 1; off < 1024; off <<= 1) {
        int v = (t >= off) ? part[t - off] : 0;
        __syncthreads();
        part[t] += v;
        __syncthreads();
    }
    int run = (t == 0) ? 0 : part[t - 1];
    for (int i = beg; i < end; ++i) {
        g_rowptr[i] = run;
        g_cursor[i] = run;
        int d = g_deg[i];
        g_dis[i] = rsqrtf((float)(d + 1));   // self-loop included, deg >= 1
        run += d;
    }
    if (t == 1023) g_rowptr[N_NODES] = part[1023];
}

__global__ void k_fill(const int* __restrict__ ei) {
    int i = blockIdx.x * blockDim.x + threadIdx.x;
    if (i < N_EDGES) {
        int s = ei[i];
        int d = ei[N_EDGES + i];
        int p = atomicAdd(&g_cursor[d], 1);
        g_col[p] = s;
    }
}

// ---------------- dense GEMM: g_bufA[N x 128] = A[N x 128] @ W[128 x 128] ----------------
// A = A_ext if non-null, else g_bufB (previous layer activation).
// block = 256 threads, tile 64 rows x 128 cols, thread microtile 4 rows x 8 cols.
__global__ __launch_bounds__(256) void k_gemm(const float* __restrict__ A_ext,
                                              const float* __restrict__ W) {
    const float* __restrict__ A = A_ext ? A_ext : g_bufB;
    const int tx = threadIdx.x & 15;   // 16 column groups (8 cols each)
    const int ty = threadIdx.x >> 4;   // 16 row groups (4 rows each)
    const int row0 = blockIdx.x * 64 + ty * 4;
    const int col0 = tx * 8;

    float acc[4][8];
#pragma unroll
    for (int r = 0; r < 4; ++r)
#pragma unroll
        for (int c = 0; c < 8; ++c) acc[r][c] = 0.f;

    const bool full = (row0 + 3 < N_NODES);

#pragma unroll 2
    for (int k4 = 0; k4 < 32; ++k4) {
        float4 a[4];
#pragma unroll
        for (int r = 0; r < 4; ++r) {
            int row = row0 + r;
            if (full || row < N_NODES)
                a[r] = *(const float4*)&A[(size_t)row * EMB + k4 * 4];
            else
                a[r] = make_float4(0.f, 0.f, 0.f, 0.f);
        }
#pragma unroll
        for (int kk = 0; kk < 4; ++kk) {
            const int k = k4 * 4 + kk;
            float4 w0 = *(const float4*)&W[k * EMB + col0];
            float4 w1 = *(const float4*)&W[k * EMB + col0 + 4];
#pragma unroll
            for (int r = 0; r < 4; ++r) {
                float av = (kk == 0) ? a[r].x : (kk == 1) ? a[r].y : (kk == 2) ? a[r].z : a[r].w;
                acc[r][0] += av * w0.x; acc[r][1] += av * w0.y;
                acc[r][2] += av * w0.z; acc[r][3] += av * w0.w;
                acc[r][4] += av * w1.x; acc[r][5] += av * w1.y;
                acc[r][6] += av * w1.z; acc[r][7] += av * w1.w;
            }
        }
    }
#pragma unroll
    for (int r = 0; r < 4; ++r) {
        int row = row0 + r;
        if (row < N_NODES) {
            *(float4*)&g_bufA[(size_t)row * EMB + col0]     = make_float4(acc[r][0], acc[r][1], acc[r][2], acc[r][3]);
            *(float4*)&g_bufA[(size_t)row * EMB + col0 + 4] = make_float4(acc[r][4], acc[r][5], acc[r][6], acc[r][7]);
        }
    }
}

// ---------------- aggregation (SpMM, warp per dst row) + bias (+ tanh) ----------------
// reads g_bufA, writes g_bufB.
// out[d] = tanh( dis[d]*( sum_{s in row d} dis[s]*h[s] + dis[d]*h[d] ) + b )
template <bool TANH>
__global__ __launch_bounds__(256) void k_agg(const float* __restrict__ bias) {
    const float* __restrict__ h = g_bufA;
    const int warp = (blockIdx.x * blockDim.x + threadIdx.x) >> 5;
    const int lane = threadIdx.x & 31;
    if (warp >= N_NODES) return;

    const int beg = g_rowptr[warp];
    const int end = g_rowptr[warp + 1];
    const int off = lane * 4;

    float4 acc = make_float4(0.f, 0.f, 0.f, 0.f);

    int j = beg;
    for (; j + 4 <= end; j += 4) {
        int s0 = g_col[j + 0], s1 = g_col[j + 1], s2 = g_col[j + 2], s3 = g_col[j + 3];
        float w0 = g_dis[s0], w1 = g_dis[s1], w2 = g_dis[s2], w3 = g_dis[s3];
        float4 v0 = *(const float4*)&h[(size_t)s0 * EMB + off];
        float4 v1 = *(const float4*)&h[(size_t)s1 * EMB + off];
        float4 v2 = *(const float4*)&h[(size_t)s2 * EMB + off];
        float4 v3 = *(const float4*)&h[(size_t)s3 * EMB + off];
        acc.x += w0 * v0.x; acc.y += w0 * v0.y; acc.z += w0 * v0.z; acc.w += w0 * v0.w;
        acc.x += w1 * v1.x; acc.y += w1 * v1.y; acc.z += w1 * v1.z; acc.w += w1 * v1.w;
        acc.x += w2 * v2.x; acc.y += w2 * v2.y; acc.z += w2 * v2.z; acc.w += w2 * v2.w;
        acc.x += w3 * v3.x; acc.y += w3 * v3.y; acc.z += w3 * v3.z; acc.w += w3 * v3.w;
    }
    for (; j < end; ++j) {
        int s = g_col[j];
        float w = g_dis[s];
        float4 v = *(const float4*)&h[(size_t)s * EMB + off];
        acc.x += w * v.x; acc.y += w * v.y; acc.z += w * v.z; acc.w += w * v.w;
    }

    const float dd = g_dis[warp];
    float4 vs = *(const float4*)&h[(size_t)warp * EMB + off];
    float4 b  = *(const float4*)&bias[off];
    float4 r;
    r.x = dd * (acc.x + dd * vs.x) + b.x;
    r.y = dd * (acc.y + dd * vs.y) + b.y;
    r.z = dd * (acc.z + dd * vs.z) + b.z;
    r.w = dd * (acc.w + dd * vs.w) + b.w;
    if (TANH) {
        r.x = tanhf(r.x); r.y = tanhf(r.y); r.z = tanhf(r.z); r.w = tanhf(r.w);
    }
    *(float4*)&g_bufB[(size_t)warp * EMB + off] = r;
}

// ---------------- global mean pool (batch is sorted, int32 graph ids) ----------------
__device__ __forceinline__ int lower_bound_i(const int* a, int n, int v) {
    int lo = 0, hi = n;
    while (lo < hi) {
        int mid = (lo + hi) >> 1;
        if (a[mid] < v) lo = mid + 1; else hi = mid;
    }
    return lo;
}

__global__ void k_pool(const int* __restrict__ batch) {
    const int g = blockIdx.x;      // 512 blocks
    const int t = threadIdx.x;     // 128 threads
    __shared__ int s_beg, s_end;
    if (t == 0) s_beg = lower_bound_i(batch, N_NODES, g);
    if (t == 1) s_end = lower_bound_i(batch, N_NODES, g + 1);
    __syncthreads();
    const int beg = s_beg, end = s_end;
    float sum = 0.f;
    for (int n = beg; n < end; ++n) sum += g_bufB[(size_t)n * EMB + t];
    int cnt = end - beg; if (cnt < 1) cnt = 1;
    g_pooled[g * EMB + t] = sum / (float)cnt;
}

// ---------------- logits + log_softmax (warp per graph) ----------------
__global__ void k_logits(const float* __restrict__ Wout, const float* __restrict__ bout,
                         float* __restrict__ out) {
    const int warp = (blockIdx.x * blockDim.x + threadIdx.x) >> 5;
    const int lane = threadIdx.x & 31;
    if (warp >= N_GRAPHS) return;

    float4 p = *(const float4*)&g_pooled[warp * EMB + lane * 4];
    const int k0 = lane * 4;

    float logit[N_CLASSES];
#pragma unroll
    for (int c = 0; c < N_CLASSES; ++c) {
        float s = p.x * Wout[(k0 + 0) * N_CLASSES + c]
                + p.y * Wout[(k0 + 1) * N_CLASSES + c]
                + p.z * Wout[(k0 + 2) * N_CLASSES + c]
                + p.w * Wout[(k0 + 3) * N_CLASSES + c];
#pragma unroll
        for (int o = 16; o > 0; o >>= 1) s += __shfl_xor_sync(0xffffffffu, s, o);
        logit[c] = s + bout[c];
    }
    float m = logit[0];
#pragma unroll
    for (int c = 1; c < N_CLASSES; ++c) m = fmaxf(m, logit[c]);
    float se = 0.f;
#pragma unroll
    for (int c = 0; c < N_CLASSES; ++c) se += expf(logit[c] - m);
    float lse = m + logf(se);
    if (lane < N_CLASSES) out[warp * N_CLASSES + lane] = logit[lane] - lse;
}

// ---------------- launch ----------------
extern "C" void kernel_launch(void* const* d_in, const int* in_sizes, int n_in,
                              void* d_out, int out_size) {
    const float* x     = (const float*)d_in[0];
    const int*   ei    = (const int*)d_in[1];    // int32! (JAX x64 disabled)
    const int*   batch = (const int*)d_in[2];    // int32!
    const float* W0 = (const float*)d_in[3];
    const float* b0 = (const float*)d_in[4];
    const float* W1 = (const float*)d_in[5];
    const float* b1 = (const float*)d_in[6];
    const float* W2 = (const float*)d_in[7];
    const float* b2 = (const float*)d_in[8];
    const float* Wout = (const float*)d_in[9];
    const float* bout = (const float*)d_in[10];
    float* out = (float*)d_out;

    // CSR build (once per launch; reused across the 3 layers)
    k_zero_deg<<<(N_NODES + 255) / 256, 256>>>();
    k_hist<<<(N_EDGES + 255) / 256, 256>>>(ei);
    k_scan<<<1, 1024>>>();
    k_fill<<<(N_EDGES + 255) / 256, 256>>>(ei);

    const int gemm_blocks = (N_NODES + 63) / 64;
    const int agg_blocks  = (N_NODES * 32 + 255) / 256;  // warp per node

    // layer 0: bufA = x @ W0 ; bufB = tanh(agg(bufA) + b0)
    k_gemm<<<gemm_blocks, 256>>>(x, W0);
    k_agg<true><<<agg_blocks, 256>>>(b0);
    // layer 1
    k_gemm<<<gemm_blocks, 256>>>(nullptr, W1);
    k_agg<true><<<agg_blocks, 256>>>(b1);
    // layer 2 (no tanh)
    k_gemm<<<gemm_blocks, 256>>>(nullptr, W2);
    k_agg<false><<<agg_blocks, 256>>>(b2);

    // pool + classifier
    k_pool<<<N_GRAPHS, EMB>>>(batch);
    k_logits<<<(N_GRAPHS * 32 + 127) / 128, 128>>>(Wout, bout, out);
}

// round 4
// speedup vs baseline: 1.4409x; 1.4409x over previous
#include <cuda_runtime.h>
#include <cuda_fp16.h>
#include <math.h>
#include <stdint.h>

#define N_NODES   50000
#define N_EDGES   1600000
#define N_FEAT    128
#define EMB       128
#define N_CLASSES 10
#define N_GRAPHS  512

// ---------------- device scratch (static, no runtime allocation) ----------------
__device__ int    g_deg[N_NODES];
__device__ int    g_rowptr[N_NODES + 1];
__device__ int    g_cursor[N_NODES];
__device__ int    g_col[N_EDGES];
__device__ float  g_dis[N_NODES];                  // deg^{-1/2} (incl. self loop)
__device__ __half g_bufA[(size_t)N_NODES * EMB];   // GEMM output, fp16 (gather payload)
__device__ float  g_bufB[(size_t)N_NODES * EMB];   // activation, fp32
__device__ float  g_pooled[N_GRAPHS * EMB];

// ---------------- CSR build ----------------
__global__ void k_zero_deg() {
    int i = blockIdx.x * blockDim.x + threadIdx.x;
    if (i < N_NODES) g_deg[i] = 0;
}

// 4 edges per thread -> 4 independent atomics in flight
__global__ void k_hist(const int* __restrict__ ei) {
    int i = (blockIdx.x * blockDim.x + threadIdx.x) * 4;
    if (i + 3 < N_EDGES) {
        int4 d = *(const int4*)&ei[N_EDGES + i];
        atomicAdd(&g_deg[d.x], 1);
        atomicAdd(&g_deg[d.y], 1);
        atomicAdd(&g_deg[d.z], 1);
        atomicAdd(&g_deg[d.w], 1);
    }
}

// single block, 1024 threads: exclusive scan of g_deg -> g_rowptr/g_cursor, dis
__global__ void k_scan() {
    __shared__ int part[1024];
    const int t = threadIdx.x;
    const int CH = (N_NODES + 1023) / 1024;   // 49
    int beg = t * CH;
    int end = beg + CH; if (end > N_NODES) end = N_NODES;
    if (beg > N_NODES) beg = N_NODES;

    int s = 0;
    for (int i = beg; i < end; ++i) s += g_deg[i];
    part[t] = s;
    __syncthreads();
    for (int off = 1; off < 1024; off <<= 1) {
        int v = (t >= off) ? part[t - off] : 0;
        __syncthreads();
        part[t] += v;
        __syncthreads();
    }
    int run = (t == 0) ? 0 : part[t - 1];
    for (int i = beg; i < end; ++i) {
        g_rowptr[i] = run;
        g_cursor[i] = run;
        int d = g_deg[i];
        g_dis[i] = rsqrtf((float)(d + 1));   // self-loop included
        run += d;
    }
    if (t == 1023) g_rowptr[N_NODES] = part[1023];
}

__global__ void k_fill(const int* __restrict__ ei) {
    int i = (blockIdx.x * blockDim.x + threadIdx.x) * 4;
    if (i + 3 < N_EDGES) {
        int4 s = *(const int4*)&ei[i];
        int4 d = *(const int4*)&ei[N_EDGES + i];
        int p0 = atomicAdd(&g_cursor[d.x], 1);
        int p1 = atomicAdd(&g_cursor[d.y], 1);
        int p2 = atomicAdd(&g_cursor[d.z], 1);
        int p3 = atomicAdd(&g_cursor[d.w], 1);
        g_col[p0] = s.x; g_col[p1] = s.y; g_col[p2] = s.z; g_col[p3] = s.w;
    }
}

// ---------------- tf32 tensor-core GEMM ----------------
// g_bufA[N x 128] (fp16) = A[N x 128] (fp32) @ W[128 x 128] (fp32, tf32-rounded)
// block = 256 threads (8 warps). Block tile: 128 rows x 128 cols.
// Warp tile: 16 rows x 128 cols = 16 x (m16n8) subtiles; k split into 2 phases of 64
// (W half staged in smem as tf32, padded stride 136 -> conflict-free B-fragment LDS).
#define SW_STRIDE 136

__device__ __forceinline__ uint32_t f2tf32(float f) {
    uint32_t u;
    asm("cvt.rna.tf32.f32 %0, %1;" : "=r"(u) : "f"(f));
    return u;
}

__global__ __launch_bounds__(256) void k_gemm(const float* __restrict__ A_ext,
                                              const float* __restrict__ W) {
    const float* __restrict__ A = A_ext ? A_ext : g_bufB;
    __shared__ uint32_t sW[64 * SW_STRIDE];

    const int tid  = threadIdx.x;
    const int warp = tid >> 5;
    const int lane = tid & 31;
    const int grp  = lane >> 2;   // 0..7
    const int q    = lane & 3;    // 0..3

    const int rowBase = blockIdx.x * 128 + warp * 16;
    const int r0 = rowBase + grp;        // rows r0, r0+8
    const bool v0 = (r0 < N_NODES);
    const bool v1 = (r0 + 8 < N_NODES);
    const float* A0 = A + (size_t)r0 * EMB;
    const float* A1 = A + (size_t)(r0 + 8) * EMB;

    float c[16][4];
#pragma unroll
    for (int nt = 0; nt < 16; ++nt)
#pragma unroll
        for (int j = 0; j < 4; ++j) c[nt][j] = 0.f;

#pragma unroll
    for (int p = 0; p < 2; ++p) {
        // stage half of W (rows p*64 .. p*64+63) into smem, tf32-rounded
        for (int idx = tid; idx < 64 * 128; idx += 256) {
            int r = idx >> 7, cc = idx & 127;
            sW[r * SW_STRIDE + cc] = f2tf32(W[(p * 64 + r) * EMB + cc]);
        }
        __syncthreads();

#pragma unroll
        for (int k0 = 0; k0 < 64; k0 += 8) {
            const int kg = p * 64 + k0 + q;    // global k for A
            // A fragment (m16n8k8 tf32 layout)
            uint32_t a0 = f2tf32(v0 ? A0[kg]     : 0.f);
            uint32_t a1 = f2tf32(v1 ? A1[kg]     : 0.f);
            uint32_t a2 = f2tf32(v0 ? A0[kg + 4] : 0.f);
            uint32_t a3 = f2tf32(v1 ? A1[kg + 4] : 0.f);

            const uint32_t* sb0 = &sW[(k0 + q) * SW_STRIDE + grp];
            const uint32_t* sb1 = sb0 + 4 * SW_STRIDE;
#pragma unroll
            for (int nt = 0; nt < 16; ++nt) {
                uint32_t b0 = sb0[nt * 8];
                uint32_t b1 = sb1[nt * 8];
                asm volatile(
                    "mma.sync.aligned.m16n8k8.row.col.f32.tf32.tf32.f32 "
                    "{%0,%1,%2,%3}, {%4,%5,%6,%7}, {%8,%9}, {%0,%1,%2,%3};"
                    : "+f"(c[nt][0]), "+f"(c[nt][1]), "+f"(c[nt][2]), "+f"(c[nt][3])
                    : "r"(a0), "r"(a1), "r"(a2), "r"(a3), "r"(b0), "r"(b1));
            }
        }
        __syncthreads();
    }

    // store C as fp16 (half2, col = n0 + 2*q is even -> 4B aligned)
    const int ccol = 2 * q;
#pragma unroll
    for (int nt = 0; nt < 16; ++nt) {
        int col = nt * 8 + ccol;
        if (v0) {
            __half2 h = __floats2half2_rn(c[nt][0], c[nt][1]);
            *(__half2*)&g_bufA[(size_t)r0 * EMB + col] = h;
        }
        if (v1) {
            __half2 h = __floats2half2_rn(c[nt][2], c[nt][3]);
            *(__half2*)&g_bufA[(size_t)(r0 + 8) * EMB + col] = h;
        }
    }
}

// ---------------- aggregation (SpMM, warp per dst row) + bias (+ tanh) ----------------
// reads g_bufA (fp16), writes g_bufB (fp32).
// out[d] = tanh( dis[d]*( sum_{s in row d} dis[s]*h[s] + dis[d]*h[d] ) + b )
__device__ __forceinline__ void acc_half4(float4& acc, float w, uint2 u) {
    float2 f0 = __half22float2(*(__half2*)&u.x);
    float2 f1 = __half22float2(*(__half2*)&u.y);
    acc.x += w * f0.x; acc.y += w * f0.y;
    acc.z += w * f1.x; acc.w += w * f1.y;
}

template <bool TANH>
__global__ __launch_bounds__(256) void k_agg(const float* __restrict__ bias) {
    const int warp = (blockIdx.x * blockDim.x + threadIdx.x) >> 5;
    const int lane = threadIdx.x & 31;
    if (warp >= N_NODES) return;

    const int beg = g_rowptr[warp];
    const int end = g_rowptr[warp + 1];
    const int off = lane * 4;   // half index within row

    float4 acc = make_float4(0.f, 0.f, 0.f, 0.f);

    int j = beg;
    for (; j + 4 <= end; j += 4) {
        int s0 = g_col[j + 0], s1 = g_col[j + 1], s2 = g_col[j + 2], s3 = g_col[j + 3];
        float w0 = g_dis[s0], w1 = g_dis[s1], w2 = g_dis[s2], w3 = g_dis[s3];
        uint2 u0 = *(const uint2*)&g_bufA[(size_t)s0 * EMB + off];
        uint2 u1 = *(const uint2*)&g_bufA[(size_t)s1 * EMB + off];
        uint2 u2 = *(const uint2*)&g_bufA[(size_t)s2 * EMB + off];
        uint2 u3 = *(const uint2*)&g_bufA[(size_t)s3 * EMB + off];
        acc_half4(acc, w0, u0);
        acc_half4(acc, w1, u1);
        acc_half4(acc, w2, u2);
        acc_half4(acc, w3, u3);
    }
    for (; j < end; ++j) {
        int s = g_col[j];
        float w = g_dis[s];
        uint2 u = *(const uint2*)&g_bufA[(size_t)s * EMB + off];
        acc_half4(acc, w, u);
    }

    const float dd = g_dis[warp];
    uint2 us = *(const uint2*)&g_bufA[(size_t)warp * EMB + off];
    float2 s0 = __half22float2(*(__half2*)&us.x);
    float2 s1 = __half22float2(*(__half2*)&us.y);
    float4 b = *(const float4*)&bias[off];
    float4 r;
    r.x = dd * (acc.x + dd * s0.x) + b.x;
    r.y = dd * (acc.y + dd * s0.y) + b.y;
    r.z = dd * (acc.z + dd * s1.x) + b.z;
    r.w = dd * (acc.w + dd * s1.y) + b.w;
    if (TANH) {
        r.x = tanhf(r.x); r.y = tanhf(r.y); r.z = tanhf(r.z); r.w = tanhf(r.w);
    }
    *(float4*)&g_bufB[(size_t)warp * EMB + off] = r;
}

// ---------------- global mean pool (batch sorted, int32 graph ids) ----------------
__device__ __forceinline__ int lower_bound_i(const int* a, int n, int v) {
    int lo = 0, hi = n;
    while (lo < hi) {
        int mid = (lo + hi) >> 1;
        if (a[mid] < v) lo = mid + 1; else hi = mid;
    }
    return lo;
}

__global__ void k_pool(const int* __restrict__ batch) {
    const int g = blockIdx.x;      // 512 blocks
    const int t = threadIdx.x;     // 128 threads
    __shared__ int s_beg, s_end;
    if (t == 0) s_beg = lower_bound_i(batch, N_NODES, g);
    if (t == 1) s_end = lower_bound_i(batch, N_NODES, g + 1);
    __syncthreads();
    const int beg = s_beg, end = s_end;
    float sum = 0.f;
    for (int n = beg; n < end; ++n) sum += g_bufB[(size_t)n * EMB + t];
    int cnt = end - beg; if (cnt < 1) cnt = 1;
    g_pooled[g * EMB + t] = sum / (float)cnt;
}

// ---------------- logits + log_softmax (warp per graph) ----------------
__global__ void k_logits(const float* __restrict__ Wout, const float* __restrict__ bout,
                         float* __restrict__ out) {
    const int warp = (blockIdx.x * blockDim.x + threadIdx.x) >> 5;
    const int lane = threadIdx.x & 31;
    if (warp >= N_GRAPHS) return;

    float4 p = *(const float4*)&g_pooled[warp * EMB + lane * 4];
    const int k0 = lane * 4;

    float logit[N_CLASSES];
#pragma unroll
    for (int c = 0; c < N_CLASSES; ++c) {
        float s = p.x * Wout[(k0 + 0) * N_CLASSES + c]
                + p.y * Wout[(k0 + 1) * N_CLASSES + c]
                + p.z * Wout[(k0 + 2) * N_CLASSES + c]
                + p.w * Wout[(k0 + 3) * N_CLASSES + c];
#pragma unroll
        for (int o = 16; o > 0; o >>= 1) s += __shfl_xor_sync(0xffffffffu, s, o);
        logit[c] = s + bout[c];
    }
    float m = logit[0];
#pragma unroll
    for (int c = 1; c < N_CLASSES; ++c) m = fmaxf(m, logit[c]);
    float se = 0.f;
#pragma unroll
    for (int c = 0; c < N_CLASSES; ++c) se += expf(logit[c] - m);
    float lse = m + logf(se);
    if (lane < N_CLASSES) out[warp * N_CLASSES + lane] = logit[lane] - lse;
}

// ---------------- launch ----------------
extern "C" void kernel_launch(void* const* d_in, const int* in_sizes, int n_in,
                              void* d_out, int out_size) {
    const float* x     = (const float*)d_in[0];
    const int*   ei    = (const int*)d_in[1];    // int32 (JAX x64 disabled)
    const int*   batch = (const int*)d_in[2];
    const float* W0 = (const float*)d_in[3];
    const float* b0 = (const float*)d_in[4];
    const float* W1 = (const float*)d_in[5];
    const float* b1 = (const float*)d_in[6];
    const float* W2 = (const float*)d_in[7];
    const float* b2 = (const float*)d_in[8];
    const float* Wout = (const float*)d_in[9];
    const float* bout = (const float*)d_in[10];
    float* out = (float*)d_out;

    // CSR build (once per launch; reused across the 3 layers)
    k_zero_deg<<<(N_NODES + 255) / 256, 256>>>();
    k_hist<<<(N_EDGES / 4 + 255) / 256, 256>>>(ei);
    k_scan<<<1, 1024>>>();
    k_fill<<<(N_EDGES / 4 + 255) / 256, 256>>>(ei);

    const int gemm_blocks = (N_NODES + 127) / 128;              // 391
    const int agg_blocks  = (N_NODES * 32 + 255) / 256;         // warp per node

    // layer 0: bufA = x @ W0 (fp16) ; bufB = tanh(agg(bufA) + b0) (fp32)
    k_gemm<<<gemm_blocks, 256>>>(x, W0);
    k_agg<true><<<agg_blocks, 256>>>(b0);
    // layer 1
    k_gemm<<<gemm_blocks, 256>>>(nullptr, W1);
    k_agg<true><<<agg_blocks, 256>>>(b1);
    // layer 2 (no tanh)
    k_gemm<<<gemm_blocks, 256>>>(nullptr, W2);
    k_agg<false><<<agg_blocks, 256>>>(b2);

    // pool + classifier
    k_pool<<<N_GRAPHS, EMB>>>(batch);
    k_logits<<<(N_GRAPHS * 32 + 127) / 128, 128>>>(Wout, bout, out);
}

// round 5
// speedup vs baseline: 2.3542x; 1.6339x over previous
#include <cuda_runtime.h>
#include <cuda_fp16.h>
#include <math.h>
#include <stdint.h>

#define N_NODES   50000
#define N_EDGES   1600000
#define N_FEAT    128
#define EMB       128
#define N_CLASSES 10
#define N_GRAPHS  512
#define ELL_W     128      // max in-degree slot count (true max ~58 for this dist)

// ---------------- device scratch (static, no runtime allocation) ----------------
__device__ int    g_cnt[N_NODES];                  // in-degree (excl. self loop)
__device__ int    g_ell[(size_t)N_NODES * ELL_W];  // ELL adjacency (src ids)
__device__ float  g_dis[N_NODES];                  // deg^{-1/2} (incl. self loop)
__device__ __half g_bufA[(size_t)N_NODES * EMB];   // pre-scaled GEMM output (fp16)
__device__ float  g_bufB[(size_t)N_NODES * EMB];   // activation, fp32
__device__ float  g_pooled[N_GRAPHS * EMB];

// ---------------- adjacency build (single atomic pass, ELL) ----------------
__global__ void k_zero_cnt() {
    int i = blockIdx.x * blockDim.x + threadIdx.x;
    if (i < N_NODES) g_cnt[i] = 0;
}

__global__ void k_fill(const int* __restrict__ ei) {
    int i = (blockIdx.x * blockDim.x + threadIdx.x) * 4;
    if (i + 3 < N_EDGES) {
        int4 s = *(const int4*)&ei[i];
        int4 d = *(const int4*)&ei[N_EDGES + i];
        int p0 = atomicAdd(&g_cnt[d.x], 1);
        int p1 = atomicAdd(&g_cnt[d.y], 1);
        int p2 = atomicAdd(&g_cnt[d.z], 1);
        int p3 = atomicAdd(&g_cnt[d.w], 1);
        if (p0 < ELL_W) g_ell[(size_t)d.x * ELL_W + p0] = s.x;
        if (p1 < ELL_W) g_ell[(size_t)d.y * ELL_W + p1] = s.y;
        if (p2 < ELL_W) g_ell[(size_t)d.z * ELL_W + p2] = s.z;
        if (p3 < ELL_W) g_ell[(size_t)d.w * ELL_W + p3] = s.w;
    }
}

__global__ void k_dis() {
    int i = blockIdx.x * blockDim.x + threadIdx.x;
    if (i < N_NODES) g_dis[i] = rsqrtf((float)(g_cnt[i] + 1));  // + self loop
}

// ---------------- tf32 tensor-core GEMM with pre-scaled fp16 epilogue ----------------
// g_bufA[r] = dis[r] * (A[r] @ W)   (fp16)
// block = 256 threads (8 warps). Block tile: 128 rows x 128 cols.
#define SW_STRIDE 136

__device__ __forceinline__ uint32_t f2tf32(float f) {
    uint32_t u;
    asm("cvt.rna.tf32.f32 %0, %1;" : "=r"(u) : "f"(f));
    return u;
}

__global__ __launch_bounds__(256) void k_gemm(const float* __restrict__ A_ext,
                                              const float* __restrict__ W) {
    const float* __restrict__ A = A_ext ? A_ext : g_bufB;
    __shared__ uint32_t sW[64 * SW_STRIDE];

    const int tid  = threadIdx.x;
    const int warp = tid >> 5;
    const int lane = tid & 31;
    const int grp  = lane >> 2;   // 0..7
    const int q    = lane & 3;    // 0..3

    const int rowBase = blockIdx.x * 128 + warp * 16;
    const int r0 = rowBase + grp;        // rows r0, r0+8
    const bool v0 = (r0 < N_NODES);
    const bool v1 = (r0 + 8 < N_NODES);
    const float* A0 = A + (size_t)r0 * EMB;
    const float* A1 = A + (size_t)(r0 + 8) * EMB;

    float c[16][4];
#pragma unroll
    for (int nt = 0; nt < 16; ++nt)
#pragma unroll
        for (int j = 0; j < 4; ++j) c[nt][j] = 0.f;

#pragma unroll
    for (int p = 0; p < 2; ++p) {
        for (int idx = tid; idx < 64 * 128; idx += 256) {
            int r = idx >> 7, cc = idx & 127;
            sW[r * SW_STRIDE + cc] = f2tf32(W[(p * 64 + r) * EMB + cc]);
        }
        __syncthreads();

#pragma unroll
        for (int k0 = 0; k0 < 64; k0 += 8) {
            const int kg = p * 64 + k0 + q;
            uint32_t a0 = f2tf32(v0 ? A0[kg]     : 0.f);
            uint32_t a1 = f2tf32(v1 ? A1[kg]     : 0.f);
            uint32_t a2 = f2tf32(v0 ? A0[kg + 4] : 0.f);
            uint32_t a3 = f2tf32(v1 ? A1[kg + 4] : 0.f);

            const uint32_t* sb0 = &sW[(k0 + q) * SW_STRIDE + grp];
            const uint32_t* sb1 = sb0 + 4 * SW_STRIDE;
#pragma unroll
            for (int nt = 0; nt < 16; ++nt) {
                uint32_t b0 = sb0[nt * 8];
                uint32_t b1 = sb1[nt * 8];
                asm volatile(
                    "mma.sync.aligned.m16n8k8.row.col.f32.tf32.tf32.f32 "
                    "{%0,%1,%2,%3}, {%4,%5,%6,%7}, {%8,%9}, {%0,%1,%2,%3};"
                    : "+f"(c[nt][0]), "+f"(c[nt][1]), "+f"(c[nt][2]), "+f"(c[nt][3])
                    : "r"(a0), "r"(a1), "r"(a2), "r"(a3), "r"(b0), "r"(b1));
            }
        }
        __syncthreads();
    }

    // epilogue: scale by dis[row], store fp16
    const float ds0 = v0 ? g_dis[r0]     : 0.f;
    const float ds1 = v1 ? g_dis[r0 + 8] : 0.f;
    const int ccol = 2 * q;
#pragma unroll
    for (int nt = 0; nt < 16; ++nt) {
        int col = nt * 8 + ccol;
        if (v0) {
            __half2 h = __floats2half2_rn(ds0 * c[nt][0], ds0 * c[nt][1]);
            *(__half2*)&g_bufA[(size_t)r0 * EMB + col] = h;
        }
        if (v1) {
            __half2 h = __floats2half2_rn(ds1 * c[nt][2], ds1 * c[nt][3]);
            *(__half2*)&g_bufA[(size_t)(r0 + 8) * EMB + col] = h;
        }
    }
}

// ---------------- aggregation (warp per dst row, ELL) + bias (+ tanh) ----------------
// bufA holds h'[r] = dis[r]*h[r]; out[d] = tanh( dis[d]*(Σ h'[s] + h'[d]) + b )
__device__ __forceinline__ void acc_half4(float4& acc, uint2 u) {
    float2 f0 = __half22float2(*(__half2*)&u.x);
    float2 f1 = __half22float2(*(__half2*)&u.y);
    acc.x += f0.x; acc.y += f0.y;
    acc.z += f1.x; acc.w += f1.y;
}

template <bool TANH>
__global__ __launch_bounds__(256) void k_agg(const float* __restrict__ bias) {
    const __half* __restrict__ h = g_bufA;
    const int d    = (blockIdx.x * blockDim.x + threadIdx.x) >> 5;
    const int lane = threadIdx.x & 31;
    if (d >= N_NODES) return;

    int len = g_cnt[d];
    if (len > ELL_W) len = ELL_W;
    const size_t base = (size_t)d * ELL_W;
    const int off = lane * 4;   // half index within row

    float4 acc = make_float4(0.f, 0.f, 0.f, 0.f);

    int j = 0;
    for (; j + 8 <= len; j += 8) {
        int4 c0 = *(const int4*)&g_ell[base + j];
        int4 c1 = *(const int4*)&g_ell[base + j + 4];
        uint2 u0 = *(const uint2*)&h[(size_t)c0.x * EMB + off];
        uint2 u1 = *(const uint2*)&h[(size_t)c0.y * EMB + off];
        uint2 u2 = *(const uint2*)&h[(size_t)c0.z * EMB + off];
        uint2 u3 = *(const uint2*)&h[(size_t)c0.w * EMB + off];
        uint2 u4 = *(const uint2*)&h[(size_t)c1.x * EMB + off];
        uint2 u5 = *(const uint2*)&h[(size_t)c1.y * EMB + off];
        uint2 u6 = *(const uint2*)&h[(size_t)c1.z * EMB + off];
        uint2 u7 = *(const uint2*)&h[(size_t)c1.w * EMB + off];
        acc_half4(acc, u0); acc_half4(acc, u1); acc_half4(acc, u2); acc_half4(acc, u3);
        acc_half4(acc, u4); acc_half4(acc, u5); acc_half4(acc, u6); acc_half4(acc, u7);
    }
    for (; j < len; ++j) {
        int s = g_ell[base + j];
        uint2 u = *(const uint2*)&h[(size_t)s * EMB + off];
        acc_half4(acc, u);
    }

    // self loop term h'[d]
    uint2 us = *(const uint2*)&h[(size_t)d * EMB + off];
    acc_half4(acc, us);

    const float dd = g_dis[d];
    float4 b = *(const float4*)&bias[off];
    float4 r;
    r.x = dd * acc.x + b.x;
    r.y = dd * acc.y + b.y;
    r.z = dd * acc.z + b.z;
    r.w = dd * acc.w + b.w;
    if (TANH) {
        r.x = tanhf(r.x); r.y = tanhf(r.y); r.z = tanhf(r.z); r.w = tanhf(r.w);
    }
    *(float4*)&g_bufB[(size_t)d * EMB + off] = r;
}

// ---------------- global mean pool (batch sorted, int32 graph ids) ----------------
__device__ __forceinline__ int lower_bound_i(const int* a, int n, int v) {
    int lo = 0, hi = n;
    while (lo < hi) {
        int mid = (lo + hi) >> 1;
        if (a[mid] < v) lo = mid + 1; else hi = mid;
    }
    return lo;
}

__global__ void k_pool(const int* __restrict__ batch) {
    const int g = blockIdx.x;      // 512 blocks
    const int t = threadIdx.x;     // 128 threads
    __shared__ int s_beg, s_end;
    if (t == 0) s_beg = lower_bound_i(batch, N_NODES, g);
    if (t == 1) s_end = lower_bound_i(batch, N_NODES, g + 1);
    __syncthreads();
    const int beg = s_beg, end = s_end;
    float sum = 0.f;
    for (int n = beg; n < end; ++n) sum += g_bufB[(size_t)n * EMB + t];
    int cnt = end - beg; if (cnt < 1) cnt = 1;
    g_pooled[g * EMB + t] = sum / (float)cnt;
}

// ---------------- logits + log_softmax (warp per graph) ----------------
__global__ void k_logits(const float* __restrict__ Wout, const float* __restrict__ bout,
                         float* __restrict__ out) {
    const int warp = (blockIdx.x * blockDim.x + threadIdx.x) >> 5;
    const int lane = threadIdx.x & 31;
    if (warp >= N_GRAPHS) return;

    float4 p = *(const float4*)&g_pooled[warp * EMB + lane * 4];
    const int k0 = lane * 4;

    float logit[N_CLASSES];
#pragma unroll
    for (int c = 0; c < N_CLASSES; ++c) {
        float s = p.x * Wout[(k0 + 0) * N_CLASSES + c]
                + p.y * Wout[(k0 + 1) * N_CLASSES + c]
                + p.z * Wout[(k0 + 2) * N_CLASSES + c]
                + p.w * Wout[(k0 + 3) * N_CLASSES + c];
#pragma unroll
        for (int o = 16; o > 0; o >>= 1) s += __shfl_xor_sync(0xffffffffu, s, o);
        logit[c] = s + bout[c];
    }
    float m = logit[0];
#pragma unroll
    for (int c = 1; c < N_CLASSES; ++c) m = fmaxf(m, logit[c]);
    float se = 0.f;
#pragma unroll
    for (int c = 0; c < N_CLASSES; ++c) se += expf(logit[c] - m);
    float lse = m + logf(se);
    if (lane < N_CLASSES) out[warp * N_CLASSES + lane] = logit[lane] - lse;
}

// ---------------- launch ----------------
extern "C" void kernel_launch(void* const* d_in, const int* in_sizes, int n_in,
                              void* d_out, int out_size) {
    const float* x     = (const float*)d_in[0];
    const int*   ei    = (const int*)d_in[1];    // int32 (JAX x64 disabled)
    const int*   batch = (const int*)d_in[2];
    const float* W0 = (const float*)d_in[3];
    const float* b0 = (const float*)d_in[4];
    const float* W1 = (const float*)d_in[5];
    const float* b1 = (const float*)d_in[6];
    const float* W2 = (const float*)d_in[7];
    const float* b2 = (const float*)d_in[8];
    const float* Wout = (const float*)d_in[9];
    const float* bout = (const float*)d_in[10];
    float* out = (float*)d_out;

    // ELL adjacency build (one atomic pass)
    k_zero_cnt<<<(N_NODES + 255) / 256, 256>>>();
    k_fill<<<(N_EDGES / 4 + 255) / 256, 256>>>(ei);
    k_dis<<<(N_NODES + 255) / 256, 256>>>();

    const int gemm_blocks = (N_NODES + 127) / 128;       // 391
    const int agg_blocks  = (N_NODES * 32 + 255) / 256;  // warp per node

    // layer 0: bufA = dis*(x @ W0) (fp16) ; bufB = tanh(dis*Σ bufA + b0)
    k_gemm<<<gemm_blocks, 256>>>(x, W0);
    k_agg<true><<<agg_blocks, 256>>>(b0);
    // layer 1
    k_gemm<<<gemm_blocks, 256>>>(nullptr, W1);
    k_agg<true><<<agg_blocks, 256>>>(b1);
    // layer 2 (no tanh)
    k_gemm<<<gemm_blocks, 256>>>(nullptr, W2);
    k_agg<false><<<agg_blocks, 256>>>(b2);

    // pool + classifier
    k_pool<<<N_GRAPHS, EMB>>>(batch);
    k_logits<<<(N_GRAPHS * 32 + 127) / 128, 128>>>(Wout, bout, out);
}

// round 6
// speedup vs baseline: 2.6576x; 1.1289x over previous
#include <cuda_runtime.h>
#include <cuda_fp16.h>
#include <math.h>
#include <stdint.h>

#define N_NODES   50000
#define N_EDGES   1600000
#define N_FEAT    128
#define EMB       128
#define N_CLASSES 10
#define N_GRAPHS  512
#define ELL_W     128      // max in-degree slot count (true max ~58 for this dist)

// ---------------- device scratch (static, no runtime allocation) ----------------
__device__ int    g_cnt[N_NODES];                  // in-degree (excl. self loop)
__device__ int    g_ell[(size_t)N_NODES * ELL_W];  // ELL adjacency (src ids)
__device__ float  g_dis[N_NODES];                  // deg^{-1/2} (incl. self loop)
__device__ __half g_bufA[(size_t)N_NODES * EMB];   // pre-scaled GEMM output (fp16)
__device__ __half g_bufB[(size_t)N_NODES * EMB];   // activation (fp16)
__device__ float  g_pooled[N_GRAPHS * EMB];

// ---------------- adjacency build (single atomic pass, ELL) ----------------
__global__ void k_zero_cnt() {
    int i = blockIdx.x * blockDim.x + threadIdx.x;
    if (i < N_NODES) g_cnt[i] = 0;
}

// 8 edges per thread -> 8 independent atomics in flight
__global__ void k_fill(const int* __restrict__ ei) {
    int i = (blockIdx.x * blockDim.x + threadIdx.x) * 8;
    if (i + 7 < N_EDGES) {
        int4 s0 = *(const int4*)&ei[i];
        int4 s1 = *(const int4*)&ei[i + 4];
        int4 d0 = *(const int4*)&ei[N_EDGES + i];
        int4 d1 = *(const int4*)&ei[N_EDGES + i + 4];
        int p0 = atomicAdd(&g_cnt[d0.x], 1);
        int p1 = atomicAdd(&g_cnt[d0.y], 1);
        int p2 = atomicAdd(&g_cnt[d0.z], 1);
        int p3 = atomicAdd(&g_cnt[d0.w], 1);
        int p4 = atomicAdd(&g_cnt[d1.x], 1);
        int p5 = atomicAdd(&g_cnt[d1.y], 1);
        int p6 = atomicAdd(&g_cnt[d1.z], 1);
        int p7 = atomicAdd(&g_cnt[d1.w], 1);
        if (p0 < ELL_W) g_ell[(size_t)d0.x * ELL_W + p0] = s0.x;
        if (p1 < ELL_W) g_ell[(size_t)d0.y * ELL_W + p1] = s0.y;
        if (p2 < ELL_W) g_ell[(size_t)d0.z * ELL_W + p2] = s0.z;
        if (p3 < ELL_W) g_ell[(size_t)d0.w * ELL_W + p3] = s0.w;
        if (p4 < ELL_W) g_ell[(size_t)d1.x * ELL_W + p4] = s1.x;
        if (p5 < ELL_W) g_ell[(size_t)d1.y * ELL_W + p5] = s1.y;
        if (p6 < ELL_W) g_ell[(size_t)d1.z * ELL_W + p6] = s1.z;
        if (p7 < ELL_W) g_ell[(size_t)d1.w * ELL_W + p7] = s1.w;
    }
}

__global__ void k_dis() {
    int i = blockIdx.x * blockDim.x + threadIdx.x;
    if (i < N_NODES) g_dis[i] = rsqrtf((float)(g_cnt[i] + 1));  // + self loop
}

// ---------------- fp16 tensor-core GEMM with pre-scaled fp16 epilogue ----------------
// g_bufA[r] = dis[r] * (A[r] @ W)   (fp16)
// block = 256 threads (8 warps). Block tile: 128 rows x 128 cols.
// Warp tile: 16 rows x 128 cols, m16n8k16 HMMA, fp32 accum.
// All of W staged once in smem, fp16, transposed [n][k] with stride 136 halves
// -> B-fragment LDS conflict-free (bank = 4*grp + q, all distinct).
#define SWT_STRIDE 136

template <bool EXT_A>
__global__ __launch_bounds__(256) void k_gemm(const float* __restrict__ A_f32,
                                              const float* __restrict__ W) {
    __shared__ __half sWT[128 * SWT_STRIDE];

    const int tid  = threadIdx.x;
    const int warp = tid >> 5;
    const int lane = tid & 31;
    const int grp  = lane >> 2;   // 0..7
    const int q    = lane & 3;    // 0..3

    // stage + transpose W (fp32 [k][n] -> fp16 [n][k])
    for (int idx = tid; idx < 128 * 128; idx += 256) {
        int k = idx >> 7, n = idx & 127;
        sWT[n * SWT_STRIDE + k] = __float2half(W[idx]);   // W[k*128+n]
    }

    const int rowBase = blockIdx.x * 128 + warp * 16;
    const int r0 = rowBase + grp;        // rows r0, r0+8
    const bool v0 = (r0 < N_NODES);
    const bool v1 = (r0 + 8 < N_NODES);

    float c[16][4];
#pragma unroll
    for (int nt = 0; nt < 16; ++nt)
#pragma unroll
        for (int j = 0; j < 4; ++j) c[nt][j] = 0.f;

    __syncthreads();

#pragma unroll
    for (int k0 = 0; k0 < 128; k0 += 16) {
        // A fragment: 4 half2 regs
        uint32_t a0, a1, a2, a3;
        const int ka = k0 + 2 * q;
        if (EXT_A) {
            const float* A0 = A_f32 + (size_t)r0 * EMB;
            const float* A1 = A_f32 + (size_t)(r0 + 8) * EMB;
            float2 f0 = v0 ? *(const float2*)&A0[ka]     : make_float2(0.f, 0.f);
            float2 f1 = v1 ? *(const float2*)&A1[ka]     : make_float2(0.f, 0.f);
            float2 f2 = v0 ? *(const float2*)&A0[ka + 8] : make_float2(0.f, 0.f);
            float2 f3 = v1 ? *(const float2*)&A1[ka + 8] : make_float2(0.f, 0.f);
            __half2 h0 = __floats2half2_rn(f0.x, f0.y);
            __half2 h1 = __floats2half2_rn(f1.x, f1.y);
            __half2 h2 = __floats2half2_rn(f2.x, f2.y);
            __half2 h3 = __floats2half2_rn(f3.x, f3.y);
            a0 = *(uint32_t*)&h0; a1 = *(uint32_t*)&h1;
            a2 = *(uint32_t*)&h2; a3 = *(uint32_t*)&h3;
        } else {
            const __half* A0 = g_bufB + (size_t)r0 * EMB;
            const __half* A1 = g_bufB + (size_t)(r0 + 8) * EMB;
            a0 = v0 ? *(const uint32_t*)&A0[ka]     : 0u;
            a1 = v1 ? *(const uint32_t*)&A1[ka]     : 0u;
            a2 = v0 ? *(const uint32_t*)&A0[ka + 8] : 0u;
            a3 = v1 ? *(const uint32_t*)&A1[ka + 8] : 0u;
        }

        const __half* sb = &sWT[grp * SWT_STRIDE + ka];
#pragma unroll
        for (int nt = 0; nt < 16; ++nt) {
            uint32_t b0 = *(const uint32_t*)&sb[nt * 8 * SWT_STRIDE];
            uint32_t b1 = *(const uint32_t*)&sb[nt * 8 * SWT_STRIDE + 8];
            asm volatile(
                "mma.sync.aligned.m16n8k16.row.col.f32.f16.f16.f32 "
                "{%0,%1,%2,%3}, {%4,%5,%6,%7}, {%8,%9}, {%0,%1,%2,%3};"
                : "+f"(c[nt][0]), "+f"(c[nt][1]), "+f"(c[nt][2]), "+f"(c[nt][3])
                : "r"(a0), "r"(a1), "r"(a2), "r"(a3), "r"(b0), "r"(b1));
        }
    }

    // epilogue: scale by dis[row], store fp16
    const float ds0 = v0 ? g_dis[r0]     : 0.f;
    const float ds1 = v1 ? g_dis[r0 + 8] : 0.f;
    const int ccol = 2 * q;
#pragma unroll
    for (int nt = 0; nt < 16; ++nt) {
        int col = nt * 8 + ccol;
        if (v0) {
            __half2 h = __floats2half2_rn(ds0 * c[nt][0], ds0 * c[nt][1]);
            *(__half2*)&g_bufA[(size_t)r0 * EMB + col] = h;
        }
        if (v1) {
            __half2 h = __floats2half2_rn(ds1 * c[nt][2], ds1 * c[nt][3]);
            *(__half2*)&g_bufA[(size_t)(r0 + 8) * EMB + col] = h;
        }
    }
}

// ---------------- aggregation (warp per dst row, ELL) + bias (+ tanh) ----------------
// bufA holds h'[r] = dis[r]*h[r]; out[d] = tanh( dis[d]*(Σ h'[s] + h'[d]) + b )
__device__ __forceinline__ void acc_half4(float4& acc, uint2 u) {
    float2 f0 = __half22float2(*(__half2*)&u.x);
    float2 f1 = __half22float2(*(__half2*)&u.y);
    acc.x += f0.x; acc.y += f0.y;
    acc.z += f1.x; acc.w += f1.y;
}

template <bool TANH>
__global__ __launch_bounds__(256) void k_agg(const float* __restrict__ bias) {
    const __half* __restrict__ h = g_bufA;
    const int d    = (blockIdx.x * blockDim.x + threadIdx.x) >> 5;
    const int lane = threadIdx.x & 31;
    if (d >= N_NODES) return;

    int len = g_cnt[d];
    if (len > ELL_W) len = ELL_W;
    const size_t base = (size_t)d * ELL_W;
    const int off = lane * 4;   // half index within row

    float4 acc = make_float4(0.f, 0.f, 0.f, 0.f);

    int j = 0;
    for (; j + 8 <= len; j += 8) {
        int4 c0 = *(const int4*)&g_ell[base + j];
        int4 c1 = *(const int4*)&g_ell[base + j + 4];
        uint2 u0 = *(const uint2*)&h[(size_t)c0.x * EMB + off];
        uint2 u1 = *(const uint2*)&h[(size_t)c0.y * EMB + off];
        uint2 u2 = *(const uint2*)&h[(size_t)c0.z * EMB + off];
        uint2 u3 = *(const uint2*)&h[(size_t)c0.w * EMB + off];
        uint2 u4 = *(const uint2*)&h[(size_t)c1.x * EMB + off];
        uint2 u5 = *(const uint2*)&h[(size_t)c1.y * EMB + off];
        uint2 u6 = *(const uint2*)&h[(size_t)c1.z * EMB + off];
        uint2 u7 = *(const uint2*)&h[(size_t)c1.w * EMB + off];
        acc_half4(acc, u0); acc_half4(acc, u1); acc_half4(acc, u2); acc_half4(acc, u3);
        acc_half4(acc, u4); acc_half4(acc, u5); acc_half4(acc, u6); acc_half4(acc, u7);
    }
    for (; j < len; ++j) {
        int s = g_ell[base + j];
        uint2 u = *(const uint2*)&h[(size_t)s * EMB + off];
        acc_half4(acc, u);
    }

    // self loop term h'[d]
    uint2 us = *(const uint2*)&h[(size_t)d * EMB + off];
    acc_half4(acc, us);

    const float dd = g_dis[d];
    float4 b = *(const float4*)&bias[off];
    float rx = dd * acc.x + b.x;
    float ry = dd * acc.y + b.y;
    float rz = dd * acc.z + b.z;
    float rw = dd * acc.w + b.w;
    if (TANH) {
        rx = tanhf(rx); ry = tanhf(ry); rz = tanhf(rz); rw = tanhf(rw);
    }
    __half2 o0 = __floats2half2_rn(rx, ry);
    __half2 o1 = __floats2half2_rn(rz, rw);
    uint2 o;
    o.x = *(uint32_t*)&o0; o.y = *(uint32_t*)&o1;
    *(uint2*)&g_bufB[(size_t)d * EMB + off] = o;
}

// ---------------- global mean pool (batch sorted, int32 graph ids) ----------------
__device__ __forceinline__ int lower_bound_i(const int* a, int n, int v) {
    int lo = 0, hi = n;
    while (lo < hi) {
        int mid = (lo + hi) >> 1;
        if (a[mid] < v) lo = mid + 1; else hi = mid;
    }
    return lo;
}

__global__ void k_pool(const int* __restrict__ batch) {
    const int g = blockIdx.x;      // 512 blocks
    const int t = threadIdx.x;     // 128 threads
    __shared__ int s_beg, s_end;
    if (t == 0) s_beg = lower_bound_i(batch, N_NODES, g);
    if (t == 1) s_end = lower_bound_i(batch, N_NODES, g + 1);
    __syncthreads();
    const int beg = s_beg, end = s_end;
    float sum = 0.f;
    for (int n = beg; n < end; ++n) sum += __half2float(g_bufB[(size_t)n * EMB + t]);
    int cnt = end - beg; if (cnt < 1) cnt = 1;
    g_pooled[g * EMB + t] = sum / (float)cnt;
}

// ---------------- logits + log_softmax (warp per graph) ----------------
__global__ void k_logits(const float* __restrict__ Wout, const float* __restrict__ bout,
                         float* __restrict__ out) {
    const int warp = (blockIdx.x * blockDim.x + threadIdx.x) >> 5;
    const int lane = threadIdx.x & 31;
    if (warp >= N_GRAPHS) return;

    float4 p = *(const float4*)&g_pooled[warp * EMB + lane * 4];
    const int k0 = lane * 4;

    float logit[N_CLASSES];
#pragma unroll
    for (int c = 0; c < N_CLASSES; ++c) {
        float s = p.x * Wout[(k0 + 0) * N_CLASSES + c]
                + p.y * Wout[(k0 + 1) * N_CLASSES + c]
                + p.z * Wout[(k0 + 2) * N_CLASSES + c]
                + p.w * Wout[(k0 + 3) * N_CLASSES + c];
#pragma unroll
        for (int o = 16; o > 0; o >>= 1) s += __shfl_xor_sync(0xffffffffu, s, o);
        logit[c] = s + bout[c];
    }
    float m = logit[0];
#pragma unroll
    for (int c = 1; c < N_CLASSES; ++c) m = fmaxf(m, logit[c]);
    float se = 0.f;
#pragma unroll
    for (int c = 0; c < N_CLASSES; ++c) se += expf(logit[c] - m);
    float lse = m + logf(se);
    if (lane < N_CLASSES) out[warp * N_CLASSES + lane] = logit[lane] - lse;
}

// ---------------- launch ----------------
extern "C" void kernel_launch(void* const* d_in, const int* in_sizes, int n_in,
                              void* d_out, int out_size) {
    const float* x     = (const float*)d_in[0];
    const int*   ei    = (const int*)d_in[1];    // int32 (JAX x64 disabled)
    const int*   batch = (const int*)d_in[2];
    const float* W0 = (const float*)d_in[3];
    const float* b0 = (const float*)d_in[4];
    const float* W1 = (const float*)d_in[5];
    const float* b1 = (const float*)d_in[6];
    const float* W2 = (const float*)d_in[7];
    const float* b2 = (const float*)d_in[8];
    const float* Wout = (const float*)d_in[9];
    const float* bout = (const float*)d_in[10];
    float* out = (float*)d_out;

    // ELL adjacency build (one atomic pass)
    k_zero_cnt<<<(N_NODES + 255) / 256, 256>>>();
    k_fill<<<(N_EDGES / 8 + 255) / 256, 256>>>(ei);
    k_dis<<<(N_NODES + 255) / 256, 256>>>();

    const int gemm_blocks = (N_NODES + 127) / 128;       // 391
    const int agg_blocks  = (N_NODES * 32 + 255) / 256;  // warp per node

    // layer 0: bufA = dis*(x @ W0) (fp16) ; bufB = tanh(dis*Σ bufA + b0) (fp16)
    k_gemm<true><<<gemm_blocks, 256>>>(x, W0);
    k_agg<true><<<agg_blocks, 256>>>(b0);
    // layer 1
    k_gemm<false><<<gemm_blocks, 256>>>(nullptr, W1);
    k_agg<true><<<agg_blocks, 256>>>(b1);
    // layer 2 (no tanh)
    k_gemm<false><<<gemm_blocks, 256>>>(nullptr, W2);
    k_agg<false><<<agg_blocks, 256>>>(b2);

    // pool + classifier
    k_pool<<<N_GRAPHS, EMB>>>(batch);
    k_logits<<<(N_GRAPHS * 32 + 127) / 128, 128>>>(Wout, bout, out);
}

// round 7
// speedup vs baseline: 2.6996x; 1.0158x over previous
#include <cuda_runtime.h>
#include <cuda_fp16.h>
#include <math.h>
#include <stdint.h>

#define N_NODES   50000
#define N_EDGES   1600000
#define N_FEAT    128
#define EMB       128
#define N_CLASSES 10
#define N_GRAPHS  512
#define ELL_W     128      // max in-degree slot count (true max ~58 for this dist)

// ---------------- device scratch (static, no runtime allocation) ----------------
__device__ int    g_cnt[N_NODES];                  // in-degree (excl. self loop)
__device__ int    g_ell[(size_t)N_NODES * ELL_W];  // ELL adjacency (src ids)
__device__ float  g_dis[N_NODES];                  // deg^{-1/2} (incl. self loop)
__device__ __half g_WT[3 * 128 * 128];             // weights fp16, transposed [n][k]
__device__ __half g_bufA[(size_t)N_NODES * EMB];   // pre-scaled GEMM output (fp16)
__device__ __half g_bufB[(size_t)N_NODES * EMB];   // activation (fp16)
__device__ float  g_pooled[N_GRAPHS * EMB];

// ---------------- adjacency build (single atomic pass, ELL) ----------------
__global__ void k_zero_cnt() {
    int i = blockIdx.x * blockDim.x + threadIdx.x;
    if (i < N_NODES) g_cnt[i] = 0;
}

// 8 edges per thread -> 8 independent atomics in flight
__global__ void k_fill(const int* __restrict__ ei) {
    int i = (blockIdx.x * blockDim.x + threadIdx.x) * 8;
    if (i + 7 < N_EDGES) {
        int4 s0 = *(const int4*)&ei[i];
        int4 s1 = *(const int4*)&ei[i + 4];
        int4 d0 = *(const int4*)&ei[N_EDGES + i];
        int4 d1 = *(const int4*)&ei[N_EDGES + i + 4];
        int p0 = atomicAdd(&g_cnt[d0.x], 1);
        int p1 = atomicAdd(&g_cnt[d0.y], 1);
        int p2 = atomicAdd(&g_cnt[d0.z], 1);
        int p3 = atomicAdd(&g_cnt[d0.w], 1);
        int p4 = atomicAdd(&g_cnt[d1.x], 1);
        int p5 = atomicAdd(&g_cnt[d1.y], 1);
        int p6 = atomicAdd(&g_cnt[d1.z], 1);
        int p7 = atomicAdd(&g_cnt[d1.w], 1);
        if (p0 < ELL_W) g_ell[(size_t)d0.x * ELL_W + p0] = s0.x;
        if (p1 < ELL_W) g_ell[(size_t)d0.y * ELL_W + p1] = s0.y;
        if (p2 < ELL_W) g_ell[(size_t)d0.z * ELL_W + p2] = s0.z;
        if (p3 < ELL_W) g_ell[(size_t)d0.w * ELL_W + p3] = s0.w;
        if (p4 < ELL_W) g_ell[(size_t)d1.x * ELL_W + p4] = s1.x;
        if (p5 < ELL_W) g_ell[(size_t)d1.y * ELL_W + p5] = s1.y;
        if (p6 < ELL_W) g_ell[(size_t)d1.z * ELL_W + p6] = s1.z;
        if (p7 < ELL_W) g_ell[(size_t)d1.w * ELL_W + p7] = s1.w;
    }
}

__global__ void k_dis() {
    int i = blockIdx.x * blockDim.x + threadIdx.x;
    if (i < N_NODES) g_dis[i] = rsqrtf((float)(g_cnt[i] + 1));  // + self loop
}

// ---------------- weight prep: fp32 [k][n] -> fp16 transposed [n][k] ----------------
__global__ void k_prep(const float* __restrict__ W0, const float* __restrict__ W1,
                       const float* __restrict__ W2) {
    int i = blockIdx.x * blockDim.x + threadIdx.x;
    if (i < 3 * 128 * 128) {
        int l = i >> 14, r = i & 16383;
        int k = r >> 7, n = r & 127;
        const float* W = (l == 0) ? W0 : (l == 1) ? W1 : W2;
        g_WT[l * 16384 + n * 128 + k] = __float2half(W[k * 128 + n]);
    }
}

// ---------------- fp16 tensor-core GEMM, persistent blocks ----------------
// g_bufA[r] = dis[r] * (A[r] @ W)   (fp16), W from g_WT (fp16, [n][k])
// block = 256 threads (8 warps), each block processes tiles blockIdx.x, +gridDim.x, ...
// W staged ONCE per block into smem (stride 136 halves -> conflict-free B LDS:
// bank = 4*grp + q, all 32 lanes distinct).
#define SWT_STRIDE 136
#define GEMM_GRID  196
#define N_TILES    ((N_NODES + 127) / 128)   // 391

template <bool EXT_A>
__global__ __launch_bounds__(256, 2) void k_gemm(const float* __restrict__ A_f32,
                                                 int widx) {
    __shared__ __half sWT[128 * SWT_STRIDE];

    const int tid  = threadIdx.x;
    const int warp = tid >> 5;
    const int lane = tid & 31;
    const int grp  = lane >> 2;   // 0..7
    const int q    = lane & 3;    // 0..3

    // stage pre-transposed fp16 W: 2048 uint4 copies (8 per thread)
    {
        const uint4* src = (const uint4*)(g_WT + widx * 16384);
#pragma unroll
        for (int i = 0; i < 8; ++i) {
            int idx = tid + i * 256;            // 0..2047
            int n   = idx >> 4;                 // row
            int c8  = (idx & 15) * 8;           // half offset within row
            *(uint4*)&sWT[n * SWT_STRIDE + c8] = src[idx];  // 272B row pitch, 16B-aligned
        }
    }
    __syncthreads();

    for (int tile = blockIdx.x; tile < N_TILES; tile += GEMM_GRID) {
        const int r0 = tile * 128 + warp * 16 + grp;   // rows r0, r0+8
        const bool v0 = (r0 < N_NODES);
        const bool v1 = (r0 + 8 < N_NODES);

        float c[16][4];
#pragma unroll
        for (int nt = 0; nt < 16; ++nt)
#pragma unroll
            for (int j = 0; j < 4; ++j) c[nt][j] = 0.f;

#pragma unroll
        for (int chunk = 0; chunk < 2; ++chunk) {
            // prefetch A fragments for 4 k-steps (16 independent loads)
            uint32_t a[4][4];
            if (EXT_A) {
                const float* A0 = A_f32 + (size_t)r0 * EMB;
                const float* A1 = A_f32 + (size_t)(r0 + 8) * EMB;
#pragma unroll
                for (int ks = 0; ks < 4; ++ks) {
                    const int ka = chunk * 64 + ks * 16 + 2 * q;
                    float2 f0 = v0 ? *(const float2*)&A0[ka]     : make_float2(0.f, 0.f);
                    float2 f1 = v1 ? *(const float2*)&A1[ka]     : make_float2(0.f, 0.f);
                    float2 f2 = v0 ? *(const float2*)&A0[ka + 8] : make_float2(0.f, 0.f);
                    float2 f3 = v1 ? *(const float2*)&A1[ka + 8] : make_float2(0.f, 0.f);
                    __half2 h0 = __floats2half2_rn(f0.x, f0.y);
                    __half2 h1 = __floats2half2_rn(f1.x, f1.y);
                    __half2 h2 = __floats2half2_rn(f2.x, f2.y);
                    __half2 h3 = __floats2half2_rn(f3.x, f3.y);
                    a[ks][0] = *(uint32_t*)&h0; a[ks][1] = *(uint32_t*)&h1;
                    a[ks][2] = *(uint32_t*)&h2; a[ks][3] = *(uint32_t*)&h3;
                }
            } else {
                const __half* A0 = g_bufB + (size_t)r0 * EMB;
                const __half* A1 = g_bufB + (size_t)(r0 + 8) * EMB;
#pragma unroll
                for (int ks = 0; ks < 4; ++ks) {
                    const int ka = chunk * 64 + ks * 16 + 2 * q;
                    a[ks][0] = v0 ? *(const uint32_t*)&A0[ka]     : 0u;
                    a[ks][1] = v1 ? *(const uint32_t*)&A1[ka]     : 0u;
                    a[ks][2] = v0 ? *(const uint32_t*)&A0[ka + 8] : 0u;
                    a[ks][3] = v1 ? *(const uint32_t*)&A1[ka + 8] : 0u;
                }
            }

#pragma unroll
            for (int ks = 0; ks < 4; ++ks) {
                const int ka = chunk * 64 + ks * 16 + 2 * q;
                const __half* sb = &sWT[grp * SWT_STRIDE + ka];
#pragma unroll
                for (int nt = 0; nt < 16; ++nt) {
                    uint32_t b0 = *(const uint32_t*)&sb[nt * 8 * SWT_STRIDE];
                    uint32_t b1 = *(const uint32_t*)&sb[nt * 8 * SWT_STRIDE + 8];
                    asm volatile(
                        "mma.sync.aligned.m16n8k16.row.col.f32.f16.f16.f32 "
                        "{%0,%1,%2,%3}, {%4,%5,%6,%7}, {%8,%9}, {%0,%1,%2,%3};"
                        : "+f"(c[nt][0]), "+f"(c[nt][1]), "+f"(c[nt][2]), "+f"(c[nt][3])
                        : "r"(a[ks][0]), "r"(a[ks][1]), "r"(a[ks][2]), "r"(a[ks][3]),
                          "r"(b0), "r"(b1));
                }
            }
        }

        // epilogue: scale by dis[row], store fp16
        const float ds0 = v0 ? g_dis[r0]     : 0.f;
        const float ds1 = v1 ? g_dis[r0 + 8] : 0.f;
        const int ccol = 2 * q;
#pragma unroll
        for (int nt = 0; nt < 16; ++nt) {
            int col = nt * 8 + ccol;
            if (v0) {
                __half2 h = __floats2half2_rn(ds0 * c[nt][0], ds0 * c[nt][1]);
                *(__half2*)&g_bufA[(size_t)r0 * EMB + col] = h;
            }
            if (v1) {
                __half2 h = __floats2half2_rn(ds1 * c[nt][2], ds1 * c[nt][3]);
                *(__half2*)&g_bufA[(size_t)(r0 + 8) * EMB + col] = h;
            }
        }
    }
}

// ---------------- aggregation (warp per dst row, ELL) + bias (+ tanh) ----------------
// bufA holds h'[r] = dis[r]*h[r]; out[d] = tanh( dis[d]*(Σ h'[s] + h'[d]) + b )
__device__ __forceinline__ void acc_half4(float4& acc, uint2 u) {
    float2 f0 = __half22float2(*(__half2*)&u.x);
    float2 f1 = __half22float2(*(__half2*)&u.y);
    acc.x += f0.x; acc.y += f0.y;
    acc.z += f1.x; acc.w += f1.y;
}

template <bool TANH>
__global__ __launch_bounds__(256) void k_agg(const float* __restrict__ bias) {
    const __half* __restrict__ h = g_bufA;
    const int d    = (blockIdx.x * blockDim.x + threadIdx.x) >> 5;
    const int lane = threadIdx.x & 31;
    if (d >= N_NODES) return;

    int len = g_cnt[d];
    if (len > ELL_W) len = ELL_W;
    const size_t base = (size_t)d * ELL_W;
    const int off = lane * 4;   // half index within row

    float4 acc = make_float4(0.f, 0.f, 0.f, 0.f);

    int j = 0;
    for (; j + 8 <= len; j += 8) {
        int4 c0 = *(const int4*)&g_ell[base + j];
        int4 c1 = *(const int4*)&g_ell[base + j + 4];
        uint2 u0 = *(const uint2*)&h[(size_t)c0.x * EMB + off];
        uint2 u1 = *(const uint2*)&h[(size_t)c0.y * EMB + off];
        uint2 u2 = *(const uint2*)&h[(size_t)c0.z * EMB + off];
        uint2 u3 = *(const uint2*)&h[(size_t)c0.w * EMB + off];
        uint2 u4 = *(const uint2*)&h[(size_t)c1.x * EMB + off];
        uint2 u5 = *(const uint2*)&h[(size_t)c1.y * EMB + off];
        uint2 u6 = *(const uint2*)&h[(size_t)c1.z * EMB + off];
        uint2 u7 = *(const uint2*)&h[(size_t)c1.w * EMB + off];
        acc_half4(acc, u0); acc_half4(acc, u1); acc_half4(acc, u2); acc_half4(acc, u3);
        acc_half4(acc, u4); acc_half4(acc, u5); acc_half4(acc, u6); acc_half4(acc, u7);
    }
    for (; j < len; ++j) {
        int s = g_ell[base + j];
        uint2 u = *(const uint2*)&h[(size_t)s * EMB + off];
        acc_half4(acc, u);
    }

    // self loop term h'[d]
    uint2 us = *(const uint2*)&h[(size_t)d * EMB + off];
    acc_half4(acc, us);

    const float dd = g_dis[d];
    float4 b = *(const float4*)&bias[off];
    float rx = dd * acc.x + b.x;
    float ry = dd * acc.y + b.y;
    float rz = dd * acc.z + b.z;
    float rw = dd * acc.w + b.w;
    if (TANH) {
        rx = tanhf(rx); ry = tanhf(ry); rz = tanhf(rz); rw = tanhf(rw);
    }
    __half2 o0 = __floats2half2_rn(rx, ry);
    __half2 o1 = __floats2half2_rn(rz, rw);
    uint2 o;
    o.x = *(uint32_t*)&o0; o.y = *(uint32_t*)&o1;
    *(uint2*)&g_bufB[(size_t)d * EMB + off] = o;
}

// ---------------- global mean pool (batch sorted, int32 graph ids) ----------------
__device__ __forceinline__ int lower_bound_i(const int* a, int n, int v) {
    int lo = 0, hi = n;
    while (lo < hi) {
        int mid = (lo + hi) >> 1;
        if (a[mid] < v) lo = mid + 1; else hi = mid;
    }
    return lo;
}

__global__ void k_pool(const int* __restrict__ batch) {
    const int g = blockIdx.x;      // 512 blocks
    const int t = threadIdx.x;     // 128 threads
    __shared__ int s_beg, s_end;
    if (t == 0) s_beg = lower_bound_i(batch, N_NODES, g);
    if (t == 1) s_end = lower_bound_i(batch, N_NODES, g + 1);
    __syncthreads();
    const int beg = s_beg, end = s_end;
    float sum = 0.f;
    for (int n = beg; n < end; ++n) sum += __half2float(g_bufB[(size_t)n * EMB + t]);
    int cnt = end - beg; if (cnt < 1) cnt = 1;
    g_pooled[g * EMB + t] = sum / (float)cnt;
}

// ---------------- logits + log_softmax (warp per graph) ----------------
__global__ void k_logits(const float* __restrict__ Wout, const float* __restrict__ bout,
                         float* __restrict__ out) {
    const int warp = (blockIdx.x * blockDim.x + threadIdx.x) >> 5;
    const int lane = threadIdx.x & 31;
    if (warp >= N_GRAPHS) return;

    float4 p = *(const float4*)&g_pooled[warp * EMB + lane * 4];
    const int k0 = lane * 4;

    float logit[N_CLASSES];
#pragma unroll
    for (int c = 0; c < N_CLASSES; ++c) {
        float s = p.x * Wout[(k0 + 0) * N_CLASSES + c]
                + p.y * Wout[(k0 + 1) * N_CLASSES + c]
                + p.z * Wout[(k0 + 2) * N_CLASSES + c]
                + p.w * Wout[(k0 + 3) * N_CLASSES + c];
#pragma unroll
        for (int o = 16; o > 0; o >>= 1) s += __shfl_xor_sync(0xffffffffu, s, o);
        logit[c] = s + bout[c];
    }
    float m = logit[0];
#pragma unroll
    for (int c = 1; c < N_CLASSES; ++c) m = fmaxf(m, logit[c]);
    float se = 0.f;
#pragma unroll
    for (int c = 0; c < N_CLASSES; ++c) se += expf(logit[c] - m);
    float lse = m + logf(se);
    if (lane < N_CLASSES) out[warp * N_CLASSES + lane] = logit[lane] - lse;
}

// ---------------- launch ----------------
extern "C" void kernel_launch(void* const* d_in, const int* in_sizes, int n_in,
                              void* d_out, int out_size) {
    const float* x     = (const float*)d_in[0];
    const int*   ei    = (const int*)d_in[1];    // int32 (JAX x64 disabled)
    const int*   batch = (const int*)d_in[2];
    const float* W0 = (const float*)d_in[3];
    const float* b0 = (const float*)d_in[4];
    const float* W1 = (const float*)d_in[5];
    const float* b1 = (const float*)d_in[6];
    const float* W2 = (const float*)d_in[7];
    const float* b2 = (const float*)d_in[8];
    const float* Wout = (const float*)d_in[9];
    const float* bout = (const float*)d_in[10];
    float* out = (float*)d_out;

    // ELL adjacency build (one atomic pass) + weight prep
    k_zero_cnt<<<(N_NODES + 255) / 256, 256>>>();
    k_fill<<<(N_EDGES / 8 + 255) / 256, 256>>>(ei);
    k_prep<<<(3 * 128 * 128 + 255) / 256, 256>>>(W0, W1, W2);
    k_dis<<<(N_NODES + 255) / 256, 256>>>();

    const int agg_blocks = (N_NODES * 32 + 255) / 256;  // warp per node

    // layer 0: bufA = dis*(x @ W0) (fp16) ; bufB = tanh(dis*Σ bufA + b0) (fp16)
    k_gemm<true><<<GEMM_GRID, 256>>>(x, 0);
    k_agg<true><<<agg_blocks, 256>>>(b0);
    // layer 1
    k_gemm<false><<<GEMM_GRID, 256>>>(nullptr, 1);
    k_agg<true><<<agg_blocks, 256>>>(b1);
    // layer 2 (no tanh)
    k_gemm<false><<<GEMM_GRID, 256>>>(nullptr, 2);
    k_agg<false><<<agg_blocks, 256>>>(b2);

    // pool + classifier
    k_pool<<<N_GRAPHS, EMB>>>(batch);
    k_logits<<<(N_GRAPHS * 32 + 127) / 128, 128>>>(Wout, bout, out);
}